// round 8
// baseline (speedup 1.0000x reference)
#include <cuda_runtime.h>
#include <cstdint>

// Shape: N=100000, E=1600000, F_in=32, F_out=64, K=3 hops.
#define NMAX 131072
#define EMAX 1703936
#define FIN  32
#define FOUT 64
#define SB   256   // scan tiles

// Static scratch. Referenced ONLY inside device code.
__device__ __align__(128) float g_h[2][(size_t)NMAX * FIN];
__device__ int   g_cnt[NMAX];        // in-degree (excl. self-loop)
__device__ float g_dinv[NMAX];       // rsqrt(deg incl. self-loop)
__device__ int   g_rowptr[NMAX + 1]; // CSR row pointers (by dst)
__device__ int   g_cursor[NMAX];     // placement cursors
__device__ __align__(16) int2 g_csr[EMAX]; // CSR: (src, weight-bits) per slot
__device__ int   g_bsum[SB];         // per-tile sums (scan phase A->C)

// ---------------------------------------------------------------------------
__global__ void k_cnt_init(int N) {
    int i = blockIdx.x * blockDim.x + threadIdx.x;
    if (i < N) g_cnt[i] = 0;
}

// Count in-degree only (reads just the dst half of edge_index; no staging).
__global__ void k_count(const int* __restrict__ ei, int E, int N) {
    int e = blockIdx.x * blockDim.x + threadIdx.x;
    if (e < E) {
        int d = ei[E + e];
        if ((unsigned)d < (unsigned)N) atomicAdd(&g_cnt[d], 1);
    }
}

// Scan phase A: tile tree-reduction -> g_bsum. Fused: dinv computed here
// (this kernel already touches every count).
__global__ void k_scan_a(int N) {
    __shared__ int sh[256];
    int b = blockIdx.x, t = threadIdx.x;
    int tile = (N + SB - 1) / SB;
    int beg = b * tile, end = min(beg + tile, N);
    int s = 0;
    for (int i = beg + t; i < end; i += 256) {
        int c = g_cnt[i];
        s += c;
        g_dinv[i] = rsqrtf((float)(c + 1));
    }
    sh[t] = s;
    __syncthreads();
#pragma unroll
    for (int off = 128; off > 0; off >>= 1) {
        if (t < off) sh[t] += sh[t + off];
        __syncthreads();
    }
    if (t == 0) g_bsum[b] = sh[0];
}

// Scan phase C (fused B): every block redundantly scans the 256 tile sums in
// smem to get its global offset, then local-scans its tile into rowptr/cursor.
__global__ void k_scan_c(int N) {
    __shared__ int shB[SB];
    __shared__ int sh[256];
    int b = blockIdx.x, t = threadIdx.x;

    int v = g_bsum[t];
    shB[t] = v;
    __syncthreads();
#pragma unroll
    for (int off = 1; off < SB; off <<= 1) {
        int u = (t >= off) ? shB[t - off] : 0;
        __syncthreads();
        shB[t] += u;
        __syncthreads();
    }
    if (b == SB - 1 && t == 0) g_rowptr[N] = shB[SB - 1];  // grand total
    int blockOff = (b == 0) ? 0 : shB[b - 1];

    int tile = (N + SB - 1) / SB;
    int beg = b * tile, end = min(beg + tile, N);
    int chunk = (tile + 255) / 256;
    int cbeg = beg + t * chunk;
    int cend = min(cbeg + chunk, end);
    int s = 0;
    for (int i = cbeg; i < cend; i++) s += g_cnt[i];
    sh[t] = s;
    __syncthreads();
#pragma unroll
    for (int off = 1; off < 256; off <<= 1) {
        int u = (t >= off) ? sh[t - off] : 0;
        __syncthreads();
        sh[t] += u;
        __syncthreads();
    }
    int run = blockOff + sh[t] - s;   // global exclusive prefix
    for (int i = cbeg; i < cend; i++) {
        g_rowptr[i] = run;
        g_cursor[i] = run;
        run += g_cnt[i];
    }
}

// Place edges into packed CSR slots (reads edge_index directly).
__global__ void k_place(const int* __restrict__ ei, int E, int N) {
    int e = blockIdx.x * blockDim.x + threadIdx.x;
    if (e < E) {
        int s = ei[e];
        int d = ei[E + e];
        if ((unsigned)s < (unsigned)N && (unsigned)d < (unsigned)N) {
            int pos = atomicAdd(&g_cursor[d], 1);
            float w = g_dinv[s] * g_dinv[d];
            g_csr[pos] = make_int2(s, __float_as_int(w));
        }
    }
}

// One propagation hop (pull/gather, no float atomics):
// out[d][:] = dinv[d]^2 * in[d][:] + sum_{e: dst=d} w_e * in[src_e][:]
// 8 lanes per dst node; each lane owns one float4 of the 128B row.
__global__ void k_hop(const float4* __restrict__ x, int srcSel, int dstSel, int N) {
    const float4* in  = (srcSel < 0) ? x : (const float4*)g_h[srcSel];
    float4*       out = (float4*)g_h[dstSel];
    int t = blockIdx.x * blockDim.x + threadIdx.x;
    int d = t >> 3;
    int j = t & 7;
    if (d >= N) return;

    float dv = g_dinv[d];
    float c = dv * dv;
    float4 a = __ldg(&in[(size_t)d * 8 + j]);
    float accx = c * a.x, accy = c * a.y, accz = c * a.z, accw = c * a.w;

    int beg = g_rowptr[d];
    int end = g_rowptr[d + 1];
#pragma unroll 4
    for (int i = beg; i < end; i++) {
        int2  cw = __ldg(&g_csr[i]);
        float w  = __int_as_float(cw.y);
        float4 v = __ldg(&in[(size_t)cw.x * 8 + j]);
        accx += w * v.x;
        accy += w * v.y;
        accz += w * v.z;
        accw += w * v.w;
    }
    out[(size_t)d * 8 + j] = make_float4(accx, accy, accz, accw);
}

// Warp-shuffle GEMM: lane l holds W[l][:] and W[l+32][:] in registers.
// Per node: 1 coalesced x load, 32 x (shfl + 2 FMA), 2 coalesced stores.
// No smem traffic at all (the old version re-read 8KB of W per node via LDS).
__global__ void k_gemm(int srcSel, const float* __restrict__ W,
                       const float* __restrict__ b, float* __restrict__ out, int N) {
    const float* h = g_h[srcSel];
    int lane = threadIdx.x & 31;
    int warp = (blockIdx.x * blockDim.x + threadIdx.x) >> 5;
    int nwarps = (gridDim.x * blockDim.x) >> 5;

    float w0[FIN], w1[FIN];
    const float4* Wv = (const float4*)W;
#pragma unroll
    for (int k4 = 0; k4 < FIN / 4; k4++) {
        float4 u = __ldg(&Wv[lane * (FIN / 4) + k4]);
        w0[4 * k4 + 0] = u.x; w0[4 * k4 + 1] = u.y;
        w0[4 * k4 + 2] = u.z; w0[4 * k4 + 3] = u.w;
        float4 v = __ldg(&Wv[(lane + 32) * (FIN / 4) + k4]);
        w1[4 * k4 + 0] = v.x; w1[4 * k4 + 1] = v.y;
        w1[4 * k4 + 2] = v.z; w1[4 * k4 + 3] = v.w;
    }
    float b0 = __ldg(&b[lane]);
    float b1 = __ldg(&b[lane + 32]);

    for (int n = warp; n < N; n += nwarps) {
        float xv = h[(size_t)n * FIN + lane];
        float a0 = b0, a1 = b1;
#pragma unroll
        for (int k = 0; k < FIN; k++) {
            float xk = __shfl_sync(0xffffffffu, xv, k);
            a0 += xk * w0[k];
            a1 += xk * w1[k];
        }
        out[(size_t)n * FOUT + lane] = a0;
        out[(size_t)n * FOUT + 32 + lane] = a1;
    }
}

// ---------------------------------------------------------------------------
extern "C" void kernel_launch(void* const* d_in, const int* in_sizes, int n_in,
                              void* d_out, int out_size) {
    const float* x  = (const float*)d_in[0];   // [N, 32] f32
    const int*   ei = (const int*)d_in[1];     // [2, E] int32
    const float* W  = (const float*)d_in[2];   // [64, 32] f32
    const float* b  = (const float*)d_in[3];   // [64] f32
    float*       out = (float*)d_out;          // [N, 64] f32

    const int N = in_sizes[0] / FIN;
    const int E = in_sizes[1] / 2;

    const int TB = 256;
    const int nBlocksN = (N + TB - 1) / TB;
    const int nBlocksE = (E + TB - 1) / TB;

    // --- CSR build ---
    k_cnt_init<<<nBlocksN, TB>>>(N);
    k_count<<<nBlocksE, TB>>>(ei, E, N);
    k_scan_a<<<SB, 256>>>(N);       // + dinv fused
    k_scan_c<<<SB, 256>>>(N);       // + block-sum scan fused
    k_place<<<nBlocksE, TB>>>(ei, E, N);

    // --- K=3 hops (pull gather, ping-pong g_h[0]/g_h[1]) ---
    const int hopBlocks = (N * 8 + TB - 1) / TB;
    k_hop<<<hopBlocks, TB>>>((const float4*)x, -1, 0, N);  // x      -> g_h[0]
    k_hop<<<hopBlocks, TB>>>((const float4*)x,  0, 1, N);  // g_h[0] -> g_h[1]
    k_hop<<<hopBlocks, TB>>>((const float4*)x,  1, 0, N);  // g_h[1] -> g_h[0]

    // --- final linear transform (warp-shuffle, register-resident W) ---
    k_gemm<<<1536, TB>>>(0, W, b, out, N);
}

// round 10
// speedup vs baseline: 1.0324x; 1.0324x over previous
#include <cuda_runtime.h>
#include <cuda_fp16.h>
#include <cstdint>

// Shape: N=100000, E=1600000, F_in=32, F_out=64, K=3 hops.
#define NMAX 131072
#define EMAX 1703936
#define FIN  32
#define FOUT 64
#define SB   256   // scan tiles

// Static scratch. Referenced ONLY inside device code.
// Intermediate h in fp16 (half2 packed in uint): halves gather traffic.
__device__ __align__(16) unsigned int g_h16[2][(size_t)NMAX * FIN / 2];
__device__ __align__(128) float g_hf[(size_t)NMAX * FIN];   // hop-3 fp32 output
__device__ int   g_cnt[NMAX];        // in-degree (zero-restored each run)
__device__ float g_dinv[NMAX];       // rsqrt(deg incl. self-loop)
__device__ int   g_rowptr[NMAX + 1]; // CSR row pointers (by dst)
__device__ int   g_cursor[NMAX];     // placement cursors
__device__ __align__(16) int2 g_csr[EMAX]; // CSR: (src, weight-bits)
__device__ int   g_bsum[SB];         // per-tile sums

// ---------------------------------------------------------------------------
// Count in-degree (g_cnt starts zero: .bss init on first run, zero-restored
// by k_scan_c on every run thereafter -> graph-replay deterministic).
__global__ void k_count(const int* __restrict__ ei, int E, int N) {
    int e = blockIdx.x * blockDim.x + threadIdx.x;
    if (e < E) {
        int d = ei[E + e];
        if ((unsigned)d < (unsigned)N) atomicAdd(&g_cnt[d], 1);
    }
}

// Scan phase A: tile tree-reduction -> g_bsum; dinv fused.
__global__ void k_scan_a(int N) {
    __shared__ int sh[256];
    int b = blockIdx.x, t = threadIdx.x;
    int tile = (N + SB - 1) / SB;
    int beg = b * tile, end = min(beg + tile, N);
    int s = 0;
    for (int i = beg + t; i < end; i += 256) {
        int c = g_cnt[i];
        s += c;
        g_dinv[i] = rsqrtf((float)(c + 1));
    }
    sh[t] = s;
    __syncthreads();
#pragma unroll
    for (int off = 128; off > 0; off >>= 1) {
        if (t < off) sh[t] += sh[t + off];
        __syncthreads();
    }
    if (t == 0) g_bsum[b] = sh[0];
}

// Scan phase C (fused B): each block scans tile sums in smem for its offset,
// local-scans its tile into rowptr/cursor, then ZERO-RESTORES g_cnt.
__global__ void k_scan_c(int N) {
    __shared__ int shB[SB];
    __shared__ int sh[256];
    int b = blockIdx.x, t = threadIdx.x;

    int v = g_bsum[t];
    shB[t] = v;
    __syncthreads();
#pragma unroll
    for (int off = 1; off < SB; off <<= 1) {
        int u = (t >= off) ? shB[t - off] : 0;
        __syncthreads();
        shB[t] += u;
        __syncthreads();
    }
    if (b == SB - 1 && t == 0) g_rowptr[N] = shB[SB - 1];
    int blockOff = (b == 0) ? 0 : shB[b - 1];

    int tile = (N + SB - 1) / SB;
    int beg = b * tile, end = min(beg + tile, N);
    int chunk = (tile + 255) / 256;
    int cbeg = beg + t * chunk;
    int cend = min(cbeg + chunk, end);
    int s = 0;
    for (int i = cbeg; i < cend; i++) s += g_cnt[i];
    sh[t] = s;
    __syncthreads();
#pragma unroll
    for (int off = 1; off < 256; off <<= 1) {
        int u = (t >= off) ? sh[t - off] : 0;
        __syncthreads();
        sh[t] += u;
        __syncthreads();
    }
    int run = blockOff + sh[t] - s;
    for (int i = cbeg; i < cend; i++) {
        g_rowptr[i] = run;
        g_cursor[i] = run;
        run += g_cnt[i];
        g_cnt[i] = 0;                 // restore invariant for next replay
    }
}

// Place edges into packed CSR slots (reads edge_index directly).
__global__ void k_place(const int* __restrict__ ei, int E, int N) {
    int e = blockIdx.x * blockDim.x + threadIdx.x;
    if (e < E) {
        int s = ei[e];
        int d = ei[E + e];
        if ((unsigned)s < (unsigned)N && (unsigned)d < (unsigned)N) {
            int pos = atomicAdd(&g_cursor[d], 1);
            float w = g_dinv[s] * g_dinv[d];
            g_csr[pos] = make_int2(s, __float_as_int(w));
        }
    }
}

// One-time convert: x fp32 -> g_h16[0] half2.
__global__ void k_conv(const float2* __restrict__ x, int n2) {
    int t = blockIdx.x * blockDim.x + threadIdx.x;
    if (t < n2) {
        float2 v = __ldg(&x[t]);
        ((__half2*)g_h16[0])[t] = __float22half2_rn(v);
    }
}

// fp16 hop: out[d][:] = dinv[d]^2*in[d][:] + sum w_e*in[src_e][:], half out.
// 8 lanes per dst row; each lane owns 4 halfs (8B = 2 half2), fp32 accum.
__global__ void k_hop16(int srcSel, int dstSel, int N) {
    const uint2* in  = (const uint2*)g_h16[srcSel];
    uint2*       out = (uint2*)g_h16[dstSel];
    int t = blockIdx.x * blockDim.x + threadIdx.x;
    int d = t >> 3;
    int j = t & 7;
    if (d >= N) return;

    float dv = g_dinv[d];
    float c = dv * dv;
    uint2 a = __ldg(&in[(size_t)d * 8 + j]);
    float2 a0 = __half22float2(*(__half2*)&a.x);
    float2 a1 = __half22float2(*(__half2*)&a.y);
    float r0 = c * a0.x, r1 = c * a0.y, r2 = c * a1.x, r3 = c * a1.y;

    int beg = g_rowptr[d];
    int end = g_rowptr[d + 1];
#pragma unroll 4
    for (int i = beg; i < end; i++) {
        int2  cw = __ldg(&g_csr[i]);
        float w  = __int_as_float(cw.y);
        uint2 v  = __ldg(&in[(size_t)cw.x * 8 + j]);
        float2 v0 = __half22float2(*(__half2*)&v.x);
        float2 v1 = __half22float2(*(__half2*)&v.y);
        r0 += w * v0.x; r1 += w * v0.y; r2 += w * v1.x; r3 += w * v1.y;
    }
    __half2 o0 = __floats2half2_rn(r0, r1);
    __half2 o1 = __floats2half2_rn(r2, r3);
    uint2 o;
    o.x = *(unsigned int*)&o0;
    o.y = *(unsigned int*)&o1;
    out[(size_t)d * 8 + j] = o;
}

// Final hop: fp16 gather -> fp32 output (g_hf) for the GEMM.
__global__ void k_hop16f(int srcSel, int N) {
    const uint2* in  = (const uint2*)g_h16[srcSel];
    float4*      out = (float4*)g_hf;
    int t = blockIdx.x * blockDim.x + threadIdx.x;
    int d = t >> 3;
    int j = t & 7;
    if (d >= N) return;

    float dv = g_dinv[d];
    float c = dv * dv;
    uint2 a = __ldg(&in[(size_t)d * 8 + j]);
    float2 a0 = __half22float2(*(__half2*)&a.x);
    float2 a1 = __half22float2(*(__half2*)&a.y);
    float r0 = c * a0.x, r1 = c * a0.y, r2 = c * a1.x, r3 = c * a1.y;

    int beg = g_rowptr[d];
    int end = g_rowptr[d + 1];
#pragma unroll 4
    for (int i = beg; i < end; i++) {
        int2  cw = __ldg(&g_csr[i]);
        float w  = __int_as_float(cw.y);
        uint2 v  = __ldg(&in[(size_t)cw.x * 8 + j]);
        float2 v0 = __half22float2(*(__half2*)&v.x);
        float2 v1 = __half22float2(*(__half2*)&v.y);
        r0 += w * v0.x; r1 += w * v0.y; r2 += w * v1.x; r3 += w * v1.y;
    }
    out[(size_t)d * 8 + j] = make_float4(r0, r1, r2, r3);
}

// Warp-shuffle GEMM: lane l holds W[l][:] and W[l+32][:] in registers.
__global__ void k_gemm(const float* __restrict__ W,
                       const float* __restrict__ b, float* __restrict__ out, int N) {
    const float* h = g_hf;
    int lane = threadIdx.x & 31;
    int warp = (blockIdx.x * blockDim.x + threadIdx.x) >> 5;
    int nwarps = (gridDim.x * blockDim.x) >> 5;

    float w0[FIN], w1[FIN];
    const float4* Wv = (const float4*)W;
#pragma unroll
    for (int k4 = 0; k4 < FIN / 4; k4++) {
        float4 u = __ldg(&Wv[lane * (FIN / 4) + k4]);
        w0[4 * k4 + 0] = u.x; w0[4 * k4 + 1] = u.y;
        w0[4 * k4 + 2] = u.z; w0[4 * k4 + 3] = u.w;
        float4 v = __ldg(&Wv[(lane + 32) * (FIN / 4) + k4]);
        w1[4 * k4 + 0] = v.x; w1[4 * k4 + 1] = v.y;
        w1[4 * k4 + 2] = v.z; w1[4 * k4 + 3] = v.w;
    }
    float b0 = __ldg(&b[lane]);
    float b1 = __ldg(&b[lane + 32]);

    for (int n = warp; n < N; n += nwarps) {
        float xv = h[(size_t)n * FIN + lane];
        float a0 = b0, a1 = b1;
#pragma unroll
        for (int k = 0; k < FIN; k++) {
            float xk = __shfl_sync(0xffffffffu, xv, k);
            a0 += xk * w0[k];
            a1 += xk * w1[k];
        }
        out[(size_t)n * FOUT + lane] = a0;
        out[(size_t)n * FOUT + 32 + lane] = a1;
    }
}

// ---------------------------------------------------------------------------
extern "C" void kernel_launch(void* const* d_in, const int* in_sizes, int n_in,
                              void* d_out, int out_size) {
    const float* x  = (const float*)d_in[0];   // [N, 32] f32
    const int*   ei = (const int*)d_in[1];     // [2, E] int32
    const float* W  = (const float*)d_in[2];   // [64, 32] f32
    const float* b  = (const float*)d_in[3];   // [64] f32
    float*       out = (float*)d_out;          // [N, 64] f32

    const int N = in_sizes[0] / FIN;
    const int E = in_sizes[1] / 2;

    const int TB = 256;
    const int nBlocksE = (E + TB - 1) / TB;

    // --- CSR build (g_cnt zero-restored by k_scan_c each run) ---
    k_count<<<nBlocksE, TB>>>(ei, E, N);
    k_scan_a<<<SB, 256>>>(N);
    k_scan_c<<<SB, 256>>>(N);
    k_place<<<nBlocksE, TB>>>(ei, E, N);

    // --- x -> fp16, then K=3 hops (fp16 gather, fp32 accumulate) ---
    const int n2 = N * (FIN / 2);
    k_conv<<<(n2 + TB - 1) / TB, TB>>>((const float2*)x, n2);

    const int hopBlocks = (N * 8 + TB - 1) / TB;
    k_hop16 <<<hopBlocks, TB>>>(0, 1, N);   // H0 -> H1
    k_hop16 <<<hopBlocks, TB>>>(1, 0, N);   // H1 -> H0
    k_hop16f<<<hopBlocks, TB>>>(0, N);      // H0 -> g_hf (fp32)

    // --- final linear transform ---
    k_gemm<<<1536, TB>>>(W, b, out, N);
}

// round 16
// speedup vs baseline: 1.0928x; 1.0586x over previous
#include <cuda_runtime.h>
#include <cuda_fp16.h>
#include <cstdint>

// Shape: N=100000, E=1600000, F_in=32, F_out=64, K=3 hops.
#define NMAX 131072
#define EMAX 1703936
#define FIN  32
#define FOUT 64
#define SB   256   // scan tiles

// Static scratch. Referenced ONLY inside device code.
// State z = dinv .* h kept in fp16 (half2 packed): z'[d] = dinv[d]^2 (z[d]+Σz[s]).
__device__ __align__(16) unsigned int g_z16[2][(size_t)NMAX * FIN / 2];
__device__ __align__(128) float g_hf[(size_t)NMAX * FIN];   // final-hop fp32 h
__device__ int   g_cnt[NMAX];        // in-degree (zero-restored each run)
__device__ float g_dinv[NMAX];       // rsqrt(deg incl. self-loop)
__device__ int   g_rowptr[NMAX + 1]; // CSR row pointers (by dst)
__device__ int   g_cursor[NMAX];     // placement cursors
__device__ int   g_csr[EMAX];        // CSR: src index only (weights algebraic)
__device__ int   g_bsum[SB];         // per-tile sums

// ---------------------------------------------------------------------------
// Count in-degree (g_cnt zero at start; k_scan_c restores zeros each replay).
__global__ void k_count(const int* __restrict__ ei, int E, int N) {
    int e = blockIdx.x * blockDim.x + threadIdx.x;
    if (e < E) {
        int d = ei[E + e];
        if ((unsigned)d < (unsigned)N) atomicAdd(&g_cnt[d], 1);
    }
}

// Scan phase A: tile tree-reduction -> g_bsum; dinv fused.
__global__ void k_scan_a(int N) {
    __shared__ int sh[256];
    int b = blockIdx.x, t = threadIdx.x;
    int tile = (N + SB - 1) / SB;
    int beg = b * tile, end = min(beg + tile, N);
    int s = 0;
    for (int i = beg + t; i < end; i += 256) {
        int c = g_cnt[i];
        s += c;
        g_dinv[i] = rsqrtf((float)(c + 1));
    }
    sh[t] = s;
    __syncthreads();
#pragma unroll
    for (int off = 128; off > 0; off >>= 1) {
        if (t < off) sh[t] += sh[t + off];
        __syncthreads();
    }
    if (t == 0) g_bsum[b] = sh[0];
}

// Scan phase C (fused B): block offset from redundant smem scan of tile sums,
// local scan into rowptr/cursor, zero-restore g_cnt.
__global__ void k_scan_c(int N) {
    __shared__ int shB[SB];
    __shared__ int sh[256];
    int b = blockIdx.x, t = threadIdx.x;

    int v = g_bsum[t];
    shB[t] = v;
    __syncthreads();
#pragma unroll
    for (int off = 1; off < SB; off <<= 1) {
        int u = (t >= off) ? shB[t - off] : 0;
        __syncthreads();
        shB[t] += u;
        __syncthreads();
    }
    if (b == SB - 1 && t == 0) g_rowptr[N] = shB[SB - 1];
    int blockOff = (b == 0) ? 0 : shB[b - 1];

    int tile = (N + SB - 1) / SB;
    int beg = b * tile, end = min(beg + tile, N);
    int chunk = (tile + 255) / 256;
    int cbeg = beg + t * chunk;
    int cend = min(cbeg + chunk, end);
    int s = 0;
    for (int i = cbeg; i < cend; i++) s += g_cnt[i];
    sh[t] = s;
    __syncthreads();
#pragma unroll
    for (int off = 1; off < 256; off <<= 1) {
        int u = (t >= off) ? sh[t - off] : 0;
        __syncthreads();
        sh[t] += u;
        __syncthreads();
    }
    int run = blockOff + sh[t] - s;
    for (int i = cbeg; i < cend; i++) {
        g_rowptr[i] = run;
        g_cursor[i] = run;
        run += g_cnt[i];
        g_cnt[i] = 0;
    }
}

// Place edges into CSR (src only — no weight computation, no dinv gathers).
__global__ void k_place(const int* __restrict__ ei, int E, int N) {
    int e = blockIdx.x * blockDim.x + threadIdx.x;
    if (e < E) {
        int s = ei[e];
        int d = ei[E + e];
        if ((unsigned)s < (unsigned)N && (unsigned)d < (unsigned)N) {
            int pos = atomicAdd(&g_cursor[d], 1);
            g_csr[pos] = s;
        }
    }
}

// One-time convert: z0 = dinv[n] * x[n][:]  (fp32 -> scaled fp16).
__global__ void k_conv(const float2* __restrict__ x, int N) {
    int t = blockIdx.x * blockDim.x + threadIdx.x;
    int n2 = N * (FIN / 2);
    if (t < n2) {
        int n = t >> 4;                 // FIN/2 == 16 half2 per row
        float dv = g_dinv[n];
        float2 v = __ldg(&x[t]);
        ((__half2*)g_z16[0])[t] = __floats2half2_rn(dv * v.x, dv * v.y);
    }
}

// fp16 z-hop: z'[d][:] = dinv[d]^2 * (z[d][:] + Σ_{e:dst=d} z[src_e][:]).
// 4 lanes per dst row; each lane owns one uint4 (8 halfs = 16B), fp32 accum.
__global__ void k_hop16(int srcSel, int dstSel, int N) {
    const uint4* in  = (const uint4*)g_z16[srcSel];
    uint4*       out = (uint4*)g_z16[dstSel];
    int t = blockIdx.x * blockDim.x + threadIdx.x;
    int d = t >> 2;
    int j = t & 3;
    if (d >= N) return;

    uint4 a = __ldg(&in[(size_t)d * 4 + j]);
    float2 p0 = __half22float2(*(__half2*)&a.x);
    float2 p1 = __half22float2(*(__half2*)&a.y);
    float2 p2 = __half22float2(*(__half2*)&a.z);
    float2 p3 = __half22float2(*(__half2*)&a.w);
    float r0 = p0.x, r1 = p0.y, r2 = p1.x, r3 = p1.y;
    float r4 = p2.x, r5 = p2.y, r6 = p3.x, r7 = p3.y;

    int beg = g_rowptr[d];
    int end = g_rowptr[d + 1];
#pragma unroll 4
    for (int i = beg; i < end; i++) {
        int   s = __ldg(&g_csr[i]);
        uint4 v = __ldg(&in[(size_t)s * 4 + j]);
        float2 q0 = __half22float2(*(__half2*)&v.x);
        float2 q1 = __half22float2(*(__half2*)&v.y);
        float2 q2 = __half22float2(*(__half2*)&v.z);
        float2 q3 = __half22float2(*(__half2*)&v.w);
        r0 += q0.x; r1 += q0.y; r2 += q1.x; r3 += q1.y;
        r4 += q2.x; r5 += q2.y; r6 += q3.x; r7 += q3.y;
    }
    float dv = g_dinv[d];
    float c = dv * dv;
    __half2 o0 = __floats2half2_rn(c * r0, c * r1);
    __half2 o1 = __floats2half2_rn(c * r2, c * r3);
    __half2 o2 = __floats2half2_rn(c * r4, c * r5);
    __half2 o3 = __floats2half2_rn(c * r6, c * r7);
    uint4 o;
    o.x = *(unsigned int*)&o0; o.y = *(unsigned int*)&o1;
    o.z = *(unsigned int*)&o2; o.w = *(unsigned int*)&o3;
    out[(size_t)d * 4 + j] = o;
}

// Final hop: h3[d][:] = dinv[d] * (z[d][:] + Σ z[src_e][:]) -> fp32 g_hf.
__global__ void k_hop16f(int srcSel, int N) {
    const uint4* in = (const uint4*)g_z16[srcSel];
    int t = blockIdx.x * blockDim.x + threadIdx.x;
    int d = t >> 2;
    int j = t & 3;
    if (d >= N) return;

    uint4 a = __ldg(&in[(size_t)d * 4 + j]);
    float2 p0 = __half22float2(*(__half2*)&a.x);
    float2 p1 = __half22float2(*(__half2*)&a.y);
    float2 p2 = __half22float2(*(__half2*)&a.z);
    float2 p3 = __half22float2(*(__half2*)&a.w);
    float r0 = p0.x, r1 = p0.y, r2 = p1.x, r3 = p1.y;
    float r4 = p2.x, r5 = p2.y, r6 = p3.x, r7 = p3.y;

    int beg = g_rowptr[d];
    int end = g_rowptr[d + 1];
#pragma unroll 4
    for (int i = beg; i < end; i++) {
        int   s = __ldg(&g_csr[i]);
        uint4 v = __ldg(&in[(size_t)s * 4 + j]);
        float2 q0 = __half22float2(*(__half2*)&v.x);
        float2 q1 = __half22float2(*(__half2*)&v.y);
        float2 q2 = __half22float2(*(__half2*)&v.z);
        float2 q3 = __half22float2(*(__half2*)&v.w);
        r0 += q0.x; r1 += q0.y; r2 += q1.x; r3 += q1.y;
        r4 += q2.x; r5 += q2.y; r6 += q3.x; r7 += q3.y;
    }
    float dv = g_dinv[d];
    float4* out = (float4*)g_hf;
    out[(size_t)d * 8 + 2 * j + 0] = make_float4(dv * r0, dv * r1, dv * r2, dv * r3);
    out[(size_t)d * 8 + 2 * j + 1] = make_float4(dv * r4, dv * r5, dv * r6, dv * r7);
}

// Warp-shuffle GEMM: lane l holds W[l][:] and W[l+32][:] in registers.
__global__ void k_gemm(const float* __restrict__ W,
                       const float* __restrict__ b, float* __restrict__ out, int N) {
    const float* h = g_hf;
    int lane = threadIdx.x & 31;
    int warp = (blockIdx.x * blockDim.x + threadIdx.x) >> 5;
    int nwarps = (gridDim.x * blockDim.x) >> 5;

    float w0[FIN], w1[FIN];
    const float4* Wv = (const float4*)W;
#pragma unroll
    for (int k4 = 0; k4 < FIN / 4; k4++) {
        float4 u = __ldg(&Wv[lane * (FIN / 4) + k4]);
        w0[4 * k4 + 0] = u.x; w0[4 * k4 + 1] = u.y;
        w0[4 * k4 + 2] = u.z; w0[4 * k4 + 3] = u.w;
        float4 v = __ldg(&Wv[(lane + 32) * (FIN / 4) + k4]);
        w1[4 * k4 + 0] = v.x; w1[4 * k4 + 1] = v.y;
        w1[4 * k4 + 2] = v.z; w1[4 * k4 + 3] = v.w;
    }
    float b0 = __ldg(&b[lane]);
    float b1 = __ldg(&b[lane + 32]);

    for (int n = warp; n < N; n += nwarps) {
        float xv = h[(size_t)n * FIN + lane];
        float a0 = b0, a1 = b1;
#pragma unroll
        for (int k = 0; k < FIN; k++) {
            float xk = __shfl_sync(0xffffffffu, xv, k);
            a0 += xk * w0[k];
            a1 += xk * w1[k];
        }
        out[(size_t)n * FOUT + lane] = a0;
        out[(size_t)n * FOUT + 32 + lane] = a1;
    }
}

// ---------------------------------------------------------------------------
extern "C" void kernel_launch(void* const* d_in, const int* in_sizes, int n_in,
                              void* d_out, int out_size) {
    const float* x  = (const float*)d_in[0];   // [N, 32] f32
    const int*   ei = (const int*)d_in[1];     // [2, E] int32
    const float* W  = (const float*)d_in[2];   // [64, 32] f32
    const float* b  = (const float*)d_in[3];   // [64] f32
    float*       out = (float*)d_out;          // [N, 64] f32

    const int N = in_sizes[0] / FIN;
    const int E = in_sizes[1] / 2;

    const int TB = 256;
    const int nBlocksE = (E + TB - 1) / TB;

    // --- CSR build (src-only entries; weights handled algebraically) ---
    k_count<<<nBlocksE, TB>>>(ei, E, N);
    k_scan_a<<<SB, 256>>>(N);
    k_scan_c<<<SB, 256>>>(N);
    k_place<<<nBlocksE, TB>>>(ei, E, N);

    // --- z0 = dinv .* x (fp16), then K=3 hops in z-space ---
    const int n2 = N * (FIN / 2);
    k_conv<<<(n2 + TB - 1) / TB, TB>>>((const float2*)x, N);

    const int hopThreads = N * 4;
    const int hopBlocks = (hopThreads + TB - 1) / TB;
    k_hop16 <<<hopBlocks, TB>>>(0, 1, N);   // z0 -> z1
    k_hop16 <<<hopBlocks, TB>>>(1, 0, N);   // z1 -> z2
    k_hop16f<<<hopBlocks, TB>>>(0, N);      // z2 -> h3 (fp32)

    // --- final linear transform ---
    k_gemm<<<1536, TB>>>(W, b, out, N);
}